// round 1
// baseline (speedup 1.0000x reference)
#include <cuda_runtime.h>
#include <cuda_bf16.h>
#include <math.h>

// ---------------------------------------------------------------------------
// DCN layer: offset/mask conv (2C->27, 3x3) + modulated deformable conv
// B=4, Cin=64, Cout=128, H=W=128, K=9, stride=1, pad=1, dil=1
// ---------------------------------------------------------------------------

#define B_   4
#define C_   64
#define O_   128
#define H_   128
#define W_   128
#define HW_  (H_*W_)

typedef unsigned long long ull;

// scratch (static device allocations are allowed)
__device__ float g_om[B_ * H_ * W_ * 28];          // per-pixel: [dy0,dx0,...,dy8,dx8, m0..m8] (m = sigmoid)
__device__ float g_wT[9 * C_ * O_];                 // wT[k][c][o] = weight[o][c][k]
__device__ float g_wT_om[128 * 9 * 28];             // wT_om[c][k][o] (o padded to 28, pad = 0)

__device__ __forceinline__ ull pack2(float lo, float hi) {
    ull r; asm("mov.b64 %0, {%1, %2};" : "=l"(r) : "f"(lo), "f"(hi)); return r;
}
__device__ __forceinline__ void unpack2(ull v, float& lo, float& hi) {
    asm("mov.b64 {%0, %1}, %2;" : "=f"(lo), "=f"(hi) : "l"(v));
}
#define FFMA2(acc, a, b) asm("fma.rn.f32x2 %0, %1, %2, %0;" : "+l"(acc) : "l"(a), "l"(b))

// ---------------------------------------------------------------------------
// Prep: weight transposes
// ---------------------------------------------------------------------------
__global__ void k_prep(const float* __restrict__ w, const float* __restrict__ w_om) {
    int i = blockIdx.x * blockDim.x + threadIdx.x;
    if (i < 9 * C_ * O_) {
        int k = i / (C_ * O_);
        int c = (i / O_) % C_;
        int o = i % O_;
        g_wT[i] = w[(o * C_ + c) * 9 + k];
    }
    if (i < 128 * 9 * 28) {
        int c = i / 252;
        int r = i % 252;
        int k = r / 28;
        int o = r % 28;
        g_wT_om[i] = (o < 27) ? w_om[(o * 128 + c) * 9 + k] : 0.f;
    }
}

// ---------------------------------------------------------------------------
// Kernel 1: offset/mask conv. feat = concat(input_feat, inter) [B,128,H,W]
// out (to g_om): 27 channels per pixel, pixel-major stride 28.
// One thread per pixel; 16x8 spatial tile per 128-thread block.
// ---------------------------------------------------------------------------
__global__ __launch_bounds__(128) void k_offconv(
    const float* __restrict__ xf, const float* __restrict__ xi,
    const float* __restrict__ b_om)
{
    __shared__ __align__(16) float wsh[16 * 252];   // 16-channel weight chunk [ci][k*28+o]

    const int tx = threadIdx.x & 15;
    const int ty = threadIdx.x >> 4;
    const int gx = blockIdx.x * 16 + tx;
    const int gy = blockIdx.y * 8 + ty;
    const int b  = blockIdx.z;

    // clamped neighbor offsets + validity multipliers (branch-free gathers)
    int   offs[9];
    float okf[9];
#pragma unroll
    for (int dy = 0; dy < 3; dy++)
#pragma unroll
        for (int dx = 0; dx < 3; dx++) {
            int yy = gy + dy - 1, xx = gx + dx - 1;
            bool ok = (yy >= 0) & (yy < H_) & (xx >= 0) & (xx < W_);
            int yc = min(max(yy, 0), H_ - 1);
            int xc = min(max(xx, 0), W_ - 1);
            offs[dy * 3 + dx] = yc * W_ + xc;
            okf[dy * 3 + dx]  = ok ? 1.f : 0.f;
        }

    ull acc2[14];
#pragma unroll
    for (int q = 0; q < 14; q++) acc2[q] = pack2(0.f, 0.f);

    for (int cc = 0; cc < 128; cc += 16) {
        __syncthreads();
        for (int idx = threadIdx.x; idx < 16 * 252; idx += 128)
            wsh[idx] = g_wT_om[cc * 252 + idx];
        __syncthreads();

#pragma unroll 4
        for (int ci = 0; ci < 16; ci++) {
            const int c = cc + ci;
            const float* s = (c < C_) ? (xf + ((b * C_ + c) << 14))
                                      : (xi + ((b * C_ + (c - C_)) << 14));
            float n[9];
#pragma unroll
            for (int k = 0; k < 9; k++) n[k] = s[offs[k]] * okf[k];

#pragma unroll
            for (int k = 0; k < 9; k++) {
                ull v2 = pack2(n[k], n[k]);
                const ulonglong2* wp = (const ulonglong2*)&wsh[ci * 252 + k * 28];
#pragma unroll
                for (int q = 0; q < 7; q++) {
                    ulonglong2 w = wp[q];
                    FFMA2(acc2[2 * q],     w.x, v2);
                    FFMA2(acc2[2 * q + 1], w.y, v2);
                }
            }
        }
    }

    // epilogue: +bias, sigmoid on mask channels, pixel-major store
    float vals[28];
#pragma unroll
    for (int q = 0; q < 7; q++) {
        unpack2(acc2[2 * q],     vals[4 * q],     vals[4 * q + 1]);
        unpack2(acc2[2 * q + 1], vals[4 * q + 2], vals[4 * q + 3]);
    }
    float* op = g_om + ((long)((b * H_ + gy) * W_) + gx) * 28;
#pragma unroll
    for (int j = 0; j < 27; j++) {
        float v = vals[j] + b_om[j];
        if (j >= 18) v = 1.f / (1.f + expf(-v));
        op[j] = v;
    }
}

// ---------------------------------------------------------------------------
// Kernel 2: modulated deformable conv.
// Block: 64 pixels (one row segment) x 128 output channels, 256 threads.
// Per tap k: coords (64 thr) -> gather v[64c][64p] to SMEM -> f32x2 GEMM.
// ---------------------------------------------------------------------------
__global__ __launch_bounds__(256) void k_deform(
    const float* __restrict__ x, const float* __restrict__ bias,
    float* __restrict__ out)
{
    __shared__ __align__(16) float v_sh[64][64];
    __shared__ float cw[4][64];     // bilinear weights * mask (zeroed when corner invalid)
    __shared__ int   coff[4][64];   // clamped corner offsets (y*W + x)

    const int b   = blockIdx.z;
    const int y   = blockIdx.y;
    const int xb0 = blockIdx.x * 64;
    const int t    = threadIdx.x;
    const int o    = t & 127;
    const int half = t >> 7;

    const float* xb = x + b * C_ * HW_;

    ull acc2[16];
#pragma unroll
    for (int q = 0; q < 16; q++) acc2[q] = pack2(0.f, 0.f);

    for (int k = 0; k < 9; k++) {
        // --- coords: 64 threads, one per pixel ---
        if (t < 64) {
            const int p   = t;
            const int px_ = xb0 + p;
            const float* omp = g_om + ((long)((b * H_ + y) * W_) + px_) * 28;
            float dy = omp[2 * k], dx = omp[2 * k + 1], m = omp[18 + k];
            float py  = (float)(y + k / 3 - 1) + dy;
            float pxf = (float)(px_ + k % 3 - 1) + dx;
            float fy = floorf(py), fx = floorf(pxf);
            int iy = (int)fy, ix = (int)fx;
            float wy = py - fy, wx = pxf - fx;
            int iy1 = iy + 1, ix1 = ix + 1;
            bool vy0 = (iy  >= 0) & (iy  < H_);
            bool vy1 = (iy1 >= 0) & (iy1 < H_);
            bool vx0 = (ix  >= 0) & (ix  < W_);
            bool vx1 = (ix1 >= 0) & (ix1 < W_);
            int cy0 = min(max(iy,  0), H_ - 1), cy1 = min(max(iy1, 0), H_ - 1);
            int cx0 = min(max(ix,  0), W_ - 1), cx1 = min(max(ix1, 0), W_ - 1);
            coff[0][p] = cy0 * W_ + cx0;
            coff[1][p] = cy0 * W_ + cx1;
            coff[2][p] = cy1 * W_ + cx0;
            coff[3][p] = cy1 * W_ + cx1;
            cw[0][p] = (vy0 & vx0) ? (1.f - wy) * (1.f - wx) * m : 0.f;
            cw[1][p] = (vy0 & vx1) ? (1.f - wy) * wx         * m : 0.f;
            cw[2][p] = (vy1 & vx0) ? wy         * (1.f - wx) * m : 0.f;
            cw[3][p] = (vy1 & vx1) ? wy         * wx         * m : 0.f;
        }
        __syncthreads();

        // --- gather: each thread does 16 channels for one pixel ---
        {
            const int p  = t & 63;
            const int c0 = (t >> 6) * 16;
            const int o00 = coff[0][p], o01 = coff[1][p], o10 = coff[2][p], o11 = coff[3][p];
            const float w00 = cw[0][p], w01 = cw[1][p], w10 = cw[2][p], w11 = cw[3][p];
            const float* pc = xb + (c0 << 14);
#pragma unroll
            for (int j = 0; j < 16; j++) {
                float v = w00 * pc[o00] + w01 * pc[o01] + w10 * pc[o10] + w11 * pc[o11];
                v_sh[c0 + j][p] = v;
                pc += HW_;
            }
        }
        __syncthreads();

        // --- GEMM: acc[o][p] += w[o][c][k] * v[c][p], packed f32x2 ---
        {
            const float* wk = g_wT + k * (C_ * O_);   // [c][o]
            const int voff = half * 32;
#pragma unroll
            for (int c = 0; c < 64; c++) {
                float wv = wk[c * O_ + o];            // coalesced across warp
                ull w2 = pack2(wv, wv);
                const ulonglong2* vp = (const ulonglong2*)&v_sh[c][voff];
#pragma unroll
                for (int q = 0; q < 8; q++) {
                    ulonglong2 vv = vp[q];            // LDS.128 broadcast
                    FFMA2(acc2[2 * q],     w2, vv.x);
                    FFMA2(acc2[2 * q + 1], w2, vv.y);
                }
            }
        }
        __syncthreads();
    }

    // --- epilogue: +bias, store 32 pixels for this output channel ---
    const float bo = bias[o];
    float* op = out + (long)((b * O_ + o) * H_ + y) * W_ + xb0 + half * 32;
#pragma unroll
    for (int q = 0; q < 8; q++) {
        float a0, a1, a2, a3;
        unpack2(acc2[2 * q],     a0, a1);
        unpack2(acc2[2 * q + 1], a2, a3);
        float4 r = make_float4(a0 + bo, a1 + bo, a2 + bo, a3 + bo);
        *(float4*)(op + 4 * q) = r;
    }
}

// ---------------------------------------------------------------------------
extern "C" void kernel_launch(void* const* d_in, const int* in_sizes, int n_in,
                              void* d_out, int out_size)
{
    const float* input_feat = (const float*)d_in[0];  // [4,64,128,128]
    const float* inter      = (const float*)d_in[1];  // [4,64,128,128]
    const float* weight     = (const float*)d_in[2];  // [128,64,3,3]
    const float* bias       = (const float*)d_in[3];  // [128]
    const float* w_om       = (const float*)d_in[4];  // [27,128,3,3]
    const float* b_om       = (const float*)d_in[5];  // [27]
    float* out = (float*)d_out;                       // [4,128,128,128]

    k_prep<<<288, 256>>>(weight, w_om);
    k_offconv<<<dim3(8, 16, 4), 128>>>(input_feat, inter, b_om);
    k_deform<<<dim3(2, 128, 4), 256>>>(input_feat, bias, out);
}

// round 5
// speedup vs baseline: 1.8629x; 1.8629x over previous
#include <cuda_runtime.h>
#include <cuda_bf16.h>
#include <math.h>
#include <stdint.h>

// ---------------------------------------------------------------------------
// DCN layer: offset/mask conv (scalar f32x2) + deformable conv (warp mma.sync
// bf16 hi/lo 3-split, fp32 accumulate). sm_103 baseline PTX only (no tcgen05:
// harness compiles for sm_103 without the 'a' suffix).
// B=4, Cin=64, Cout=128, H=W=128, K=9, stride=1, pad=1, dil=1
// ---------------------------------------------------------------------------

#define B_   4
#define C_   64
#define O_   128
#define H_   128
#define W_   128
#define HW_  (H_*W_)

typedef unsigned long long ull;

// ---- scratch (static device allocations allowed) --------------------------
__device__ float g_om[B_ * H_ * W_ * 28];     // per-pixel [dy0,dx0,..,dy8,dx8,m0..m8]
__device__ float g_wT_om[128 * 9 * 28];       // offconv weights [c][k][o28]
// deform weights packed in mma.sync A-fragment layout:
// idx = ((((tap*2+split)*4+kstep)*8+wtile)*32+lane)*4 + reg   (uint32 = 2 bf16)
__device__ __align__(16) uint32_t g_wfrag[9 * 2 * 4 * 8 * 32 * 4];

// ---- helpers --------------------------------------------------------------
__device__ __forceinline__ ull pack2(float lo, float hi) {
    ull r; asm("mov.b64 %0, {%1, %2};" : "=l"(r) : "f"(lo), "f"(hi)); return r;
}
__device__ __forceinline__ void unpack2(ull v, float& lo, float& hi) {
    asm("mov.b64 {%0, %1}, %2;" : "=f"(lo), "=f"(hi) : "l"(v));
}
#define FFMA2(acc, a, b) asm("fma.rn.f32x2 %0, %1, %2, %0;" : "+l"(acc) : "l"(a), "l"(b))

__device__ __forceinline__ void mma_bf16(float* d, const uint32_t* a,
                                         uint32_t b0, uint32_t b1) {
    asm("mma.sync.aligned.m16n8k16.row.col.f32.bf16.bf16.f32 "
        "{%0,%1,%2,%3}, {%4,%5,%6,%7}, {%8,%9}, {%0,%1,%2,%3};"
        : "+f"(d[0]), "+f"(d[1]), "+f"(d[2]), "+f"(d[3])
        : "r"(a[0]), "r"(a[1]), "r"(a[2]), "r"(a[3]), "r"(b0), "r"(b1));
}

__device__ __forceinline__ uint32_t bf16x2(float v0, float v1) {
    __nv_bfloat162 h;
    h.x = __float2bfloat16(v0);
    h.y = __float2bfloat16(v1);
    return *(uint32_t*)&h;
}

// ---------------------------------------------------------------------------
// Prep: weight transforms
// ---------------------------------------------------------------------------
__global__ void k_prep(const float* __restrict__ w, const float* __restrict__ w_om) {
    int i = blockIdx.x * blockDim.x + threadIdx.x;
    // deform weights -> A-fragment layout, hi/lo bf16 split
    if (i < 9 * 2 * 4 * 8 * 32 * 4) {
        int reg  = i & 3;
        int lane = (i >> 2) & 31;
        int wt   = (i >> 7) & 7;
        int ks   = (i >> 10) & 3;
        int split= (i >> 12) & 1;
        int tap  = i >> 13;
        int gid = lane >> 2, tid4 = lane & 3;
        int row  = gid + ((reg & 1) ? 8 : 0);
        int colb = 2 * tid4 + ((reg & 2) ? 8 : 0);
        int o = wt * 16 + row;
        int c0 = ks * 16 + colb;
        float w0 = w[(o * C_ + c0) * 9 + tap];
        float w1 = w[(o * C_ + c0 + 1) * 9 + tap];
        __nv_bfloat16 h0 = __float2bfloat16(w0);
        __nv_bfloat16 h1 = __float2bfloat16(w1);
        float v0, v1;
        if (split == 0) { v0 = __bfloat162float(h0); v1 = __bfloat162float(h1); }
        else { v0 = w0 - __bfloat162float(h0); v1 = w1 - __bfloat162float(h1); }
        g_wfrag[i] = bf16x2(v0, v1);
    }
    // offconv weight transpose (o padded to 28)
    if (i < 128 * 9 * 28) {
        int c = i / 252, r = i % 252, k = r / 28, o = r % 28;
        g_wT_om[i] = (o < 27) ? w_om[(o * 128 + c) * 9 + k] : 0.f;
    }
}

// ---------------------------------------------------------------------------
// Kernel 1: offset/mask conv (scalar f32x2 path, unchanged from R1)
// ---------------------------------------------------------------------------
__global__ __launch_bounds__(128) void k_offconv(
    const float* __restrict__ xf, const float* __restrict__ xi,
    const float* __restrict__ b_om)
{
    __shared__ __align__(16) float wsh[16 * 252];

    const int tx = threadIdx.x & 15;
    const int ty = threadIdx.x >> 4;
    const int gx = blockIdx.x * 16 + tx;
    const int gy = blockIdx.y * 8 + ty;
    const int b  = blockIdx.z;

    int   offs[9];
    float okf[9];
#pragma unroll
    for (int dy = 0; dy < 3; dy++)
#pragma unroll
        for (int dx = 0; dx < 3; dx++) {
            int yy = gy + dy - 1, xx = gx + dx - 1;
            bool ok = (yy >= 0) & (yy < H_) & (xx >= 0) & (xx < W_);
            int yc = min(max(yy, 0), H_ - 1);
            int xc = min(max(xx, 0), W_ - 1);
            offs[dy * 3 + dx] = yc * W_ + xc;
            okf[dy * 3 + dx]  = ok ? 1.f : 0.f;
        }

    ull acc2[14];
#pragma unroll
    for (int q = 0; q < 14; q++) acc2[q] = pack2(0.f, 0.f);

    for (int cc = 0; cc < 128; cc += 16) {
        __syncthreads();
        for (int idx = threadIdx.x; idx < 16 * 252; idx += 128)
            wsh[idx] = g_wT_om[cc * 252 + idx];
        __syncthreads();

#pragma unroll 4
        for (int ci = 0; ci < 16; ci++) {
            const int c = cc + ci;
            const float* s = (c < C_) ? (xf + ((b * C_ + c) << 14))
                                      : (xi + ((b * C_ + (c - C_)) << 14));
            float n[9];
#pragma unroll
            for (int k = 0; k < 9; k++) n[k] = s[offs[k]] * okf[k];

#pragma unroll
            for (int k = 0; k < 9; k++) {
                ull v2 = pack2(n[k], n[k]);
                const ulonglong2* wp = (const ulonglong2*)&wsh[ci * 252 + k * 28];
#pragma unroll
                for (int q = 0; q < 7; q++) {
                    ulonglong2 w = wp[q];
                    FFMA2(acc2[2 * q],     w.x, v2);
                    FFMA2(acc2[2 * q + 1], w.y, v2);
                }
            }
        }
    }

    float vals[28];
#pragma unroll
    for (int q = 0; q < 7; q++) {
        unpack2(acc2[2 * q],     vals[4 * q],     vals[4 * q + 1]);
        unpack2(acc2[2 * q + 1], vals[4 * q + 2], vals[4 * q + 3]);
    }
    float* op = g_om + ((long)((b * H_ + gy) * W_) + gx) * 28;
#pragma unroll
    for (int j = 0; j < 27; j++) {
        float v = vals[j] + b_om[j];
        if (j >= 18) v = 1.f / (1.f + expf(-v));
        op[j] = v;
    }
}

// ---------------------------------------------------------------------------
// Kernel 2: deformable conv via mma.sync (bf16 3-split, fp32 acc).
// One block = one image row. D[128 o][128 p]; warp w owns o-stripe [16w,16w+16).
// v_sh layout: [split][p*72 + c] bf16 (stride 72 => conflict-free LDS/STS).
// ---------------------------------------------------------------------------
#define VSTRIDE 72

__global__ __launch_bounds__(256, 2) void k_deform_mma(
    const float* __restrict__ x, const float* __restrict__ bias,
    float* __restrict__ out)
{
    __shared__ __nv_bfloat16 vsh[2][128 * VSTRIDE];
    __shared__ float cw[4][128];
    __shared__ int   cof[4][128];

    const int t    = threadIdx.x;
    const int lane = t & 31;
    const int wid  = t >> 5;            // = o-tile index, 8 warps
    const int gid  = lane >> 2;
    const int tid4 = lane & 3;
    const int y    = blockIdx.x;
    const int b    = blockIdx.y;

    const float* xb = x + b * (C_ * HW_);

    float acc[16][4];
#pragma unroll
    for (int pt = 0; pt < 16; pt++)
#pragma unroll
        for (int q = 0; q < 4; q++) acc[pt][q] = 0.f;

    for (int k = 0; k < 9; k++) {
        // --- per-pixel coords: clamped corners + mask-premultiplied weights ---
        if (t < 128) {
            const int p = t;
            const float* omp = g_om + ((long)((b * H_ + y) * W_) + p) * 28;
            float dy = omp[2 * k], dx = omp[2 * k + 1], m = omp[18 + k];
            float py  = (float)(y + k / 3 - 1) + dy;
            float pxf = (float)(p + k % 3 - 1) + dx;
            float fy = floorf(py), fx = floorf(pxf);
            int iy = (int)fy, ix = (int)fx;
            float wy = py - fy, wx = pxf - fx;
            int iy1 = iy + 1, ix1 = ix + 1;
            bool vy0 = (iy  >= 0) & (iy  < H_);
            bool vy1 = (iy1 >= 0) & (iy1 < H_);
            bool vx0 = (ix  >= 0) & (ix  < W_);
            bool vx1 = (ix1 >= 0) & (ix1 < W_);
            int cy0 = min(max(iy,  0), H_ - 1), cy1 = min(max(iy1, 0), H_ - 1);
            int cx0 = min(max(ix,  0), W_ - 1), cx1 = min(max(ix1, 0), W_ - 1);
            cof[0][p] = cy0 * W_ + cx0;
            cof[1][p] = cy0 * W_ + cx1;
            cof[2][p] = cy1 * W_ + cx0;
            cof[3][p] = cy1 * W_ + cx1;
            cw[0][p] = (vy0 & vx0) ? (1.f - wy) * (1.f - wx) * m : 0.f;
            cw[1][p] = (vy0 & vx1) ? (1.f - wy) * wx         * m : 0.f;
            cw[2][p] = (vy1 & vx0) ? wy         * (1.f - wx) * m : 0.f;
            cw[3][p] = (vy1 & vx1) ? wy         * wx         * m : 0.f;
        }
        __syncthreads();

        // --- gather: v[c][p] fp32 -> bf16 hi/lo pairs into vsh[p][c] ---
        {
            const int p  = t & 127;
            const int c0 = (t >> 7) * 32;
            const int o00 = cof[0][p], o01 = cof[1][p];
            const int o10 = cof[2][p], o11 = cof[3][p];
            const float w00 = cw[0][p], w01 = cw[1][p];
            const float w10 = cw[2][p], w11 = cw[3][p];
            const float* pc = xb + (c0 << 14);
            uint32_t* bh = (uint32_t*)&vsh[0][p * VSTRIDE + c0];
            uint32_t* bl = (uint32_t*)&vsh[1][p * VSTRIDE + c0];
#pragma unroll 8
            for (int j = 0; j < 32; j += 2) {
                float v0 = fmaf(w00, pc[o00], fmaf(w01, pc[o01],
                           fmaf(w10, pc[o10], w11 * pc[o11])));
                const float* pc1 = pc + HW_;
                float v1 = fmaf(w00, pc1[o00], fmaf(w01, pc1[o01],
                           fmaf(w10, pc1[o10], w11 * pc1[o11])));
                __nv_bfloat16 h0 = __float2bfloat16(v0);
                __nv_bfloat16 h1 = __float2bfloat16(v1);
                float l0 = v0 - __bfloat162float(h0);
                float l1 = v1 - __bfloat162float(h1);
                __nv_bfloat162 hv; hv.x = h0; hv.y = h1;
                bh[j >> 1] = *(uint32_t*)&hv;
                bl[j >> 1] = bf16x2(l0, l1);
                pc += 2 * HW_;
            }
        }
        __syncthreads();

        // --- mma phase: 3 split-products, K = 64 ch = 4 ksteps ---
        {
            const uint32_t* wf_h = g_wfrag + ((((k * 2 + 0) * 4) * 8 + wid) * 32 + lane) * 4;
            const uint32_t* wf_l = g_wfrag + ((((k * 2 + 1) * 4) * 8 + wid) * 32 + lane) * 4;
#pragma unroll
            for (int ks = 0; ks < 4; ks++) {
                uint4 ahv = *(const uint4*)(wf_h + ks * (8 * 32 * 4));
                uint4 alv = *(const uint4*)(wf_l + ks * (8 * 32 * 4));
                uint32_t ah[4] = {ahv.x, ahv.y, ahv.z, ahv.w};
                uint32_t al[4] = {alv.x, alv.y, alv.z, alv.w};
                const int coff = ks * 16 + 2 * tid4;
#pragma unroll
                for (int pt = 0; pt < 16; pt++) {
                    const int pr = (pt * 8 + gid) * VSTRIDE + coff;
                    uint32_t bh0 = *(const uint32_t*)&vsh[0][pr];
                    uint32_t bh1 = *(const uint32_t*)&vsh[0][pr + 8];
                    uint32_t bl0 = *(const uint32_t*)&vsh[1][pr];
                    uint32_t bl1 = *(const uint32_t*)&vsh[1][pr + 8];
                    mma_bf16(acc[pt], ah, bh0, bh1);
                    mma_bf16(acc[pt], ah, bl0, bl1);
                    mma_bf16(acc[pt], al, bh0, bh1);
                }
            }
        }
        __syncthreads();
    }

    // --- epilogue: +bias, direct float2 stores (pixel pairs contiguous) ---
    const int o0 = wid * 16 + gid;
    const int o1 = o0 + 8;
    const float bo0 = bias[o0];
    const float bo1 = bias[o1];
    float* r0 = out + (((long)(b * O_ + o0) * H_ + y) << 7);
    float* r1 = out + (((long)(b * O_ + o1) * H_ + y) << 7);
#pragma unroll
    for (int pt = 0; pt < 16; pt++) {
        const int p = pt * 8 + 2 * tid4;
        float2 v0 = make_float2(acc[pt][0] + bo0, acc[pt][1] + bo0);
        float2 v1 = make_float2(acc[pt][2] + bo1, acc[pt][3] + bo1);
        *(float2*)(r0 + p) = v0;
        *(float2*)(r1 + p) = v1;
    }
}

// ---------------------------------------------------------------------------
extern "C" void kernel_launch(void* const* d_in, const int* in_sizes, int n_in,
                              void* d_out, int out_size)
{
    const float* input_feat = (const float*)d_in[0];  // [4,64,128,128]
    const float* inter      = (const float*)d_in[1];  // [4,64,128,128]
    const float* weight     = (const float*)d_in[2];  // [128,64,3,3]
    const float* bias       = (const float*)d_in[3];  // [128]
    const float* w_om       = (const float*)d_in[4];  // [27,128,3,3]
    const float* b_om       = (const float*)d_in[5];  // [27]
    float* out = (float*)d_out;                       // [4,128,128,128]

    k_prep<<<288, 256>>>(weight, w_om);
    k_offconv<<<dim3(8, 16, 4), 128>>>(input_feat, inter, b_om);
    k_deform_mma<<<dim3(128, 4), 256>>>(input_feat, bias, out);
}

// round 6
// speedup vs baseline: 2.6448x; 1.4197x over previous
#include <cuda_runtime.h>
#include <cuda_bf16.h>
#include <math.h>
#include <stdint.h>

// ---------------------------------------------------------------------------
// DCN layer, all-tensor-pipe version (mma.sync bf16 hi/lo 3-split):
//   k_prep       : weight fragment packing (deform + offconv)
//   k_prep_feat  : feat=concat(xf,xi) -> packed bf16 hi/lo uint32
//   k_offconv_mma: offset/mask conv via mma.sync
//   k_deform_mma : modulated deformable conv via mma.sync
// B=4, Cin=64, Cout=128, H=W=128, K=9, stride=1, pad=1, dil=1
// ---------------------------------------------------------------------------

#define B_   4
#define C_   64
#define O_   128
#define H_   128
#define W_   128
#define HW_  (H_*W_)

// ---- scratch --------------------------------------------------------------
__device__ float g_om[B_ * H_ * W_ * 28];   // per-pixel [dy0,dx0,..,dy8,dx8,m0..m9]
// deform weights, A-frag layout: ((((tap*2+split)*4+ks)*8+wt)*32+lane)*4+reg
__device__ __align__(16) uint32_t g_wfrag[9 * 2 * 4 * 8 * 32 * 4];
// offconv weights, A-frag layout: ((((tap*2+split)*8+ks)*2+mi)*32+lane)*4+reg
__device__ __align__(16) uint32_t g_wofrag[9 * 2 * 8 * 2 * 32 * 4];
// feat bf16 hi/lo packed: [b][c(128)][y][x], hi in low16, lo in high16
__device__ __align__(16) uint32_t g_fhl[B_ * 128 * HW_];

// ---- helpers --------------------------------------------------------------
__device__ __forceinline__ void mma_bf16(float* d, const uint32_t* a,
                                         uint32_t b0, uint32_t b1) {
    asm("mma.sync.aligned.m16n8k16.row.col.f32.bf16.bf16.f32 "
        "{%0,%1,%2,%3}, {%4,%5,%6,%7}, {%8,%9}, {%0,%1,%2,%3};"
        : "+f"(d[0]), "+f"(d[1]), "+f"(d[2]), "+f"(d[3])
        : "r"(a[0]), "r"(a[1]), "r"(a[2]), "r"(a[3]), "r"(b0), "r"(b1));
}
__device__ __forceinline__ uint32_t bf16x2(float v0, float v1) {
    __nv_bfloat162 h;
    h.x = __float2bfloat16(v0);
    h.y = __float2bfloat16(v1);
    return *(uint32_t*)&h;
}
__device__ __forceinline__ uint32_t pack_hl(float v) {
    __nv_bfloat16 h = __float2bfloat16(v);
    __nv_bfloat16 l = __float2bfloat16(v - __bfloat162float(h));
    return (uint32_t)*(uint16_t*)&h | ((uint32_t)*(uint16_t*)&l << 16);
}

// ---------------------------------------------------------------------------
// Prep: weight fragment packing
// ---------------------------------------------------------------------------
__global__ void k_prep(const float* __restrict__ w, const float* __restrict__ w_om) {
    int i = blockIdx.x * blockDim.x + threadIdx.x;
    // deform weights [o=128][c=64] per tap
    if (i < 9 * 2 * 4 * 8 * 32 * 4) {
        int reg  = i & 3;
        int lane = (i >> 2) & 31;
        int wt   = (i >> 7) & 7;
        int ks   = (i >> 10) & 3;
        int split= (i >> 12) & 1;
        int tap  = i >> 13;
        int gid = lane >> 2, tid4 = lane & 3;
        int row  = gid + ((reg & 1) ? 8 : 0);
        int colb = 2 * tid4 + ((reg & 2) ? 8 : 0);
        int o = wt * 16 + row;
        int c0 = ks * 16 + colb;
        float w0 = w[(o * C_ + c0) * 9 + tap];
        float w1 = w[(o * C_ + c0 + 1) * 9 + tap];
        __nv_bfloat16 h0 = __float2bfloat16(w0);
        __nv_bfloat16 h1 = __float2bfloat16(w1);
        float v0, v1;
        if (split == 0) { v0 = __bfloat162float(h0); v1 = __bfloat162float(h1); }
        else { v0 = w0 - __bfloat162float(h0); v1 = w1 - __bfloat162float(h1); }
        g_wfrag[i] = bf16x2(v0, v1);
    }
    // offconv weights [o=27(pad32)][c=128] per tap
    if (i < 9 * 2 * 8 * 2 * 32 * 4) {
        int reg  = i & 3;
        int lane = (i >> 2) & 31;
        int mi   = (i >> 7) & 1;
        int ks   = (i >> 8) & 7;
        int split= (i >> 11) & 1;
        int tap  = i >> 12;
        int gid = lane >> 2, tid4 = lane & 3;
        int row  = gid + ((reg & 1) ? 8 : 0);
        int colb = 2 * tid4 + ((reg & 2) ? 8 : 0);
        int o = mi * 16 + row;
        int c0 = ks * 16 + colb;
        float w0 = 0.f, w1 = 0.f;
        if (o < 27) {
            w0 = w_om[(o * 128 + c0) * 9 + tap];
            w1 = w_om[(o * 128 + c0 + 1) * 9 + tap];
        }
        __nv_bfloat16 h0 = __float2bfloat16(w0);
        __nv_bfloat16 h1 = __float2bfloat16(w1);
        float v0, v1;
        if (split == 0) { v0 = __bfloat162float(h0); v1 = __bfloat162float(h1); }
        else { v0 = w0 - __bfloat162float(h0); v1 = w1 - __bfloat162float(h1); }
        g_wofrag[i] = bf16x2(v0, v1);
    }
}

// ---------------------------------------------------------------------------
// Prep: feat -> packed bf16 hi/lo. grid 8192 x 256, 4 elems/thread.
// ---------------------------------------------------------------------------
__global__ __launch_bounds__(256) void k_prep_feat(
    const float* __restrict__ xf, const float* __restrict__ xi)
{
    long base = ((long)blockIdx.x * 256 + threadIdx.x) * 4;
    int b = (int)(base >> 21);
    int c = (int)(base >> 14) & 127;
    int off = (int)base & 16383;           // y*128 + x
    const float* src = (c < C_) ? (xf + (((long)(b * C_ + c)) << 14) + off)
                                : (xi + (((long)(b * C_ + (c - C_))) << 14) + off);
    float4 v = *(const float4*)src;
    uint4 r;
    r.x = pack_hl(v.x); r.y = pack_hl(v.y);
    r.z = pack_hl(v.z); r.w = pack_hl(v.w);
    *(uint4*)&g_fhl[base] = r;
}

// ---------------------------------------------------------------------------
// Kernel 1: offset/mask conv via mma.sync.
// Block = one image row. D[32 o][128 p], K = 3 dy x (slab) x 3 dx x 128 ch.
// SMEM slab: [p+1][c] bf16, rows 0..129 (rows 0,129 = zero pad), stride 132.
// ---------------------------------------------------------------------------
#define VS2 132

__global__ __launch_bounds__(256, 2) void k_offconv_mma(
    const float* __restrict__ b_om)
{
    extern __shared__ __align__(16) __nv_bfloat16 osm[];
    __nv_bfloat16* vh = osm;                   // 130*132
    __nv_bfloat16* vl = osm + 130 * VS2;       // 130*132

    const int t    = threadIdx.x;
    const int lane = t & 31;
    const int wid  = t >> 5;
    const int gid  = lane >> 2;
    const int tid4 = lane & 3;
    const int y    = blockIdx.x;
    const int b    = blockIdx.y;

    const int mi = wid & 1;                    // m-tile (o rows mi*16..)
    const int nb = (wid >> 1) * 32;            // n base (32 px per warp pair)

    // zero pad rows 0 and 129
    if (t < VS2) {
        vh[t] = __nv_bfloat16(0.f);            vl[t] = __nv_bfloat16(0.f);
        vh[129 * VS2 + t] = __nv_bfloat16(0.f); vl[129 * VS2 + t] = __nv_bfloat16(0.f);
    }

    float acc[4][4];
#pragma unroll
    for (int nt = 0; nt < 4; nt++)
#pragma unroll
        for (int q = 0; q < 4; q++) acc[nt][q] = 0.f;

    for (int dy = 0; dy < 3; dy++) {
        __syncthreads();
        // --- gather+transpose slab for source row y+dy-1 ---
        {
            const int p  = t & 127;
            const int ch = (t >> 7) * 64;      // 64 channels per half
            const int ysrc = y + dy - 1;
            uint32_t* dh = (uint32_t*)&vh[(p + 1) * VS2 + ch];
            uint32_t* dl = (uint32_t*)&vl[(p + 1) * VS2 + ch];
            if (ysrc >= 0 && ysrc < H_) {
                const uint32_t* s = g_fhl + (((long)(b * 128 + ch)) << 14) + (ysrc << 7) + p;
#pragma unroll 8
                for (int j = 0; j < 64; j += 2) {
                    uint32_t u0 = s[0];
                    uint32_t u1 = s[16384];
                    s += 32768;
                    dh[j >> 1] = (u0 & 0xffffu) | (u1 << 16);
                    dl[j >> 1] = (u0 >> 16) | (u1 & 0xffff0000u);
                }
            } else {
#pragma unroll
                for (int j = 0; j < 32; j++) { dh[j] = 0u; dl[j] = 0u; }
            }
        }
        __syncthreads();

        // --- 3 dx-taps on this slab ---
#pragma unroll
        for (int dx = 0; dx < 3; dx++) {
            const int tap = dy * 3 + dx;
            const uint32_t* wf_h = g_wofrag + ((((tap * 2 + 0) * 8) * 2 + mi) * 32 + lane) * 4;
            const uint32_t* wf_l = g_wofrag + ((((tap * 2 + 1) * 8) * 2 + mi) * 32 + lane) * 4;
#pragma unroll
            for (int ks = 0; ks < 8; ks++) {
                uint4 ahv = *(const uint4*)(wf_h + ks * (2 * 32 * 4));
                uint4 alv = *(const uint4*)(wf_l + ks * (2 * 32 * 4));
                uint32_t ah[4] = {ahv.x, ahv.y, ahv.z, ahv.w};
                uint32_t al[4] = {alv.x, alv.y, alv.z, alv.w};
                const int cb = ks * 16 + 2 * tid4;
#pragma unroll
                for (int nt = 0; nt < 4; nt++) {
                    const int row = nb + nt * 8 + gid + dx;   // p + dx (pad row +1, shift -1)
                    const int ad = row * VS2 + cb;
                    uint32_t bh0 = *(const uint32_t*)&vh[ad];
                    uint32_t bh1 = *(const uint32_t*)&vh[ad + 8];
                    uint32_t bl0 = *(const uint32_t*)&vl[ad];
                    uint32_t bl1 = *(const uint32_t*)&vl[ad + 8];
                    mma_bf16(acc[nt], ah, bh0, bh1);
                    mma_bf16(acc[nt], ah, bl0, bl1);
                    mma_bf16(acc[nt], al, bh0, bh1);
                }
            }
        }
    }

    // --- epilogue: +bias, sigmoid on mask rows, store to g_om ---
    const int r0 = mi * 16 + gid;
    const int r1 = r0 + 8;
    const float bo0 = b_om[r0];                       // r0 <= 23 < 27 always
    const float bo1 = (r1 < 27) ? b_om[r1] : 0.f;
    float* omb = g_om + ((long)((b * H_ + y) * W_)) * 28;
#pragma unroll
    for (int nt = 0; nt < 4; nt++) {
        const int p = nb + nt * 8 + 2 * tid4;
        float v0 = acc[nt][0] + bo0, v1 = acc[nt][1] + bo0;
        float v2 = acc[nt][2] + bo1, v3 = acc[nt][3] + bo1;
        if (r0 >= 18) { v0 = 1.f / (1.f + expf(-v0)); v1 = 1.f / (1.f + expf(-v1)); }
        if (r1 >= 18) { v2 = 1.f / (1.f + expf(-v2)); v3 = 1.f / (1.f + expf(-v3)); }
        omb[(long)p * 28 + r0]       = v0;
        omb[(long)(p + 1) * 28 + r0] = v1;
        if (r1 < 27) {
            omb[(long)p * 28 + r1]       = v2;
            omb[(long)(p + 1) * 28 + r1] = v3;
        }
    }
}

// ---------------------------------------------------------------------------
// Kernel 2: deformable conv via mma.sync (unchanged from R5).
// ---------------------------------------------------------------------------
#define VSTRIDE 72

__global__ __launch_bounds__(256, 2) void k_deform_mma(
    const float* __restrict__ x, const float* __restrict__ bias,
    float* __restrict__ out)
{
    __shared__ __nv_bfloat16 vsh[2][128 * VSTRIDE];
    __shared__ float cw[4][128];
    __shared__ int   cof[4][128];

    const int t    = threadIdx.x;
    const int lane = t & 31;
    const int wid  = t >> 5;
    const int gid  = lane >> 2;
    const int tid4 = lane & 3;
    const int y    = blockIdx.x;
    const int b    = blockIdx.y;

    const float* xb = x + b * (C_ * HW_);

    float acc[16][4];
#pragma unroll
    for (int pt = 0; pt < 16; pt++)
#pragma unroll
        for (int q = 0; q < 4; q++) acc[pt][q] = 0.f;

    for (int k = 0; k < 9; k++) {
        if (t < 128) {
            const int p = t;
            const float* omp = g_om + ((long)((b * H_ + y) * W_) + p) * 28;
            float dy = omp[2 * k], dx = omp[2 * k + 1], m = omp[18 + k];
            float py  = (float)(y + k / 3 - 1) + dy;
            float pxf = (float)(p + k % 3 - 1) + dx;
            float fy = floorf(py), fx = floorf(pxf);
            int iy = (int)fy, ix = (int)fx;
            float wy = py - fy, wx = pxf - fx;
            int iy1 = iy + 1, ix1 = ix + 1;
            bool vy0 = (iy  >= 0) & (iy  < H_);
            bool vy1 = (iy1 >= 0) & (iy1 < H_);
            bool vx0 = (ix  >= 0) & (ix  < W_);
            bool vx1 = (ix1 >= 0) & (ix1 < W_);
            int cy0 = min(max(iy,  0), H_ - 1), cy1 = min(max(iy1, 0), H_ - 1);
            int cx0 = min(max(ix,  0), W_ - 1), cx1 = min(max(ix1, 0), W_ - 1);
            cof[0][p] = cy0 * W_ + cx0;
            cof[1][p] = cy0 * W_ + cx1;
            cof[2][p] = cy1 * W_ + cx0;
            cof[3][p] = cy1 * W_ + cx1;
            cw[0][p] = (vy0 & vx0) ? (1.f - wy) * (1.f - wx) * m : 0.f;
            cw[1][p] = (vy0 & vx1) ? (1.f - wy) * wx         * m : 0.f;
            cw[2][p] = (vy1 & vx0) ? wy         * (1.f - wx) * m : 0.f;
            cw[3][p] = (vy1 & vx1) ? wy         * wx         * m : 0.f;
        }
        __syncthreads();

        {
            const int p  = t & 127;
            const int c0 = (t >> 7) * 32;
            const int o00 = cof[0][p], o01 = cof[1][p];
            const int o10 = cof[2][p], o11 = cof[3][p];
            const float w00 = cw[0][p], w01 = cw[1][p];
            const float w10 = cw[2][p], w11 = cw[3][p];
            const float* pc = xb + (c0 << 14);
            uint32_t* bh = (uint32_t*)&vsh[0][p * VSTRIDE + c0];
            uint32_t* bl = (uint32_t*)&vsh[1][p * VSTRIDE + c0];
#pragma unroll 8
            for (int j = 0; j < 32; j += 2) {
                float v0 = fmaf(w00, pc[o00], fmaf(w01, pc[o01],
                           fmaf(w10, pc[o10], w11 * pc[o11])));
                const float* pc1 = pc + HW_;
                float v1 = fmaf(w00, pc1[o00], fmaf(w01, pc1[o01],
                           fmaf(w10, pc1[o10], w11 * pc1[o11])));
                __nv_bfloat16 h0 = __float2bfloat16(v0);
                __nv_bfloat16 h1 = __float2bfloat16(v1);
                float l0 = v0 - __bfloat162float(h0);
                float l1 = v1 - __bfloat162float(h1);
                __nv_bfloat162 hv; hv.x = h0; hv.y = h1;
                bh[j >> 1] = *(uint32_t*)&hv;
                bl[j >> 1] = bf16x2(l0, l1);
                pc += 2 * HW_;
            }
        }
        __syncthreads();

        {
            const uint32_t* wf_h = g_wfrag + ((((k * 2 + 0) * 4) * 8 + wid) * 32 + lane) * 4;
            const uint32_t* wf_l = g_wfrag + ((((k * 2 + 1) * 4) * 8 + wid) * 32 + lane) * 4;
#pragma unroll
            for (int ks = 0; ks < 4; ks++) {
                uint4 ahv = *(const uint4*)(wf_h + ks * (8 * 32 * 4));
                uint4 alv = *(const uint4*)(wf_l + ks * (8 * 32 * 4));
                uint32_t ah[4] = {ahv.x, ahv.y, ahv.z, ahv.w};
                uint32_t al[4] = {alv.x, alv.y, alv.z, alv.w};
                const int coff = ks * 16 + 2 * tid4;
#pragma unroll
                for (int pt = 0; pt < 16; pt++) {
                    const int pr = (pt * 8 + gid) * VSTRIDE + coff;
                    uint32_t bh0 = *(const uint32_t*)&vsh[0][pr];
                    uint32_t bh1 = *(const uint32_t*)&vsh[0][pr + 8];
                    uint32_t bl0 = *(const uint32_t*)&vsh[1][pr];
                    uint32_t bl1 = *(const uint32_t*)&vsh[1][pr + 8];
                    mma_bf16(acc[pt], ah, bh0, bh1);
                    mma_bf16(acc[pt], ah, bl0, bl1);
                    mma_bf16(acc[pt], al, bh0, bh1);
                }
            }
        }
        __syncthreads();
    }

    const int o0 = wid * 16 + gid;
    const int o1 = o0 + 8;
    const float bo0 = bias[o0];
    const float bo1 = bias[o1];
    float* r0 = out + (((long)(b * O_ + o0) * H_ + y) << 7);
    float* r1 = out + (((long)(b * O_ + o1) * H_ + y) << 7);
#pragma unroll
    for (int pt = 0; pt < 16; pt++) {
        const int p = pt * 8 + 2 * tid4;
        float2 v0 = make_float2(acc[pt][0] + bo0, acc[pt][1] + bo0);
        float2 v1 = make_float2(acc[pt][2] + bo1, acc[pt][3] + bo1);
        *(float2*)(r0 + p) = v0;
        *(float2*)(r1 + p) = v1;
    }
}

// ---------------------------------------------------------------------------
extern "C" void kernel_launch(void* const* d_in, const int* in_sizes, int n_in,
                              void* d_out, int out_size)
{
    const float* input_feat = (const float*)d_in[0];  // [4,64,128,128]
    const float* inter      = (const float*)d_in[1];  // [4,64,128,128]
    const float* weight     = (const float*)d_in[2];  // [128,64,3,3]
    const float* bias       = (const float*)d_in[3];  // [128]
    const float* w_om       = (const float*)d_in[4];  // [27,128,3,3]
    const float* b_om       = (const float*)d_in[5];  // [27]
    float* out = (float*)d_out;                       // [4,128,128,128]

    static int smem_set = 0;
    if (!smem_set) {
        cudaFuncSetAttribute(k_offconv_mma,
                             cudaFuncAttributeMaxDynamicSharedMemorySize,
                             2 * 130 * VS2 * (int)sizeof(__nv_bfloat16));
        smem_set = 1;
    }

    k_prep<<<288, 256>>>(weight, w_om);
    k_prep_feat<<<8192, 256>>>(input_feat, inter);
    k_offconv_mma<<<dim3(128, 4), 256,
                    2 * 130 * VS2 * sizeof(__nv_bfloat16)>>>(b_om);
    k_deform_mma<<<dim3(128, 4), 256>>>(input_feat, bias, out);
}